// round 9
// baseline (speedup 1.0000x reference)
#include <cuda_runtime.h>
#include <cuda_bf16.h>
#include <cstdint>

// loss = || sum_spatial(input_c) - sum_spatial(target_c) ||^2 / C^2
// input/target: (1, 128, 512, 512) fp32 contiguous.
// 1024 blocks x 512 thr. Warp-specialized streams: warps 0-7 read `in`,
// warps 8-15 read `tgt` over the same 128KB region; each warp walks one
// contiguous 16KB run (maximal per-stream DRAM page locality).
// Fused last-block finalize, fixed-order sums (bit-deterministic).

#define NCH   128
#define HW    (512 * 512)          // 262144 elements per channel
#define SPLIT 8                    // blocks per channel
#define NBLK  (NCH * SPLIT)        // 1024 blocks
#define NTHR  512
#define NWARP (NTHR / 32)          // 16 warps

__device__ float        g_partial[NBLK];
__device__ unsigned int g_count;   // zero-init at load; last block resets it

__global__ __launch_bounds__(NTHR) void fused_loss_kernel(
    const float4* __restrict__ in, const float4* __restrict__ tgt,
    float* __restrict__ out)
{
    const int blk = blockIdx.x;              // 0 .. NBLK-1
    const int c   = blk >> 3;                // channel
    const int s   = blk & (SPLIT - 1);       // split within channel

    const int vec_per_chan = HW / 4;                 // 65536 float4/channel
    const int vec_per_blk  = vec_per_chan / SPLIT;   // 8192 float4/block

    const int wid = threadIdx.x >> 5;        // 0..15
    const int lid = threadIdx.x & 31;

    const size_t base = (size_t)c * vec_per_chan + (size_t)s * vec_per_blk;

    // Warps 0-7: in (+); warps 8-15: tgt (-). Each warp owns a contiguous
    // run of vec_per_blk/8 = 1024 float4 (16 KB), 32 iterations of 512B.
    const int sub_warp   = wid & 7;                       // 0..7 within stream
    const int vec_per_w  = vec_per_blk / 8;               // 1024
    const float4* src    = (wid < 8) ? in : tgt;
    const float  sign    = (wid < 8) ? 1.0f : -1.0f;
    const float4* p      = src + base + (size_t)sub_warp * vec_per_w;

    float acc0 = 0.0f, acc1 = 0.0f;
    #pragma unroll 8
    for (int i = lid; i < vec_per_w; i += 32) {
        float4 a = __ldg(p + i);
        acc0 += a.x + a.y;
        acc1 += a.z + a.w;
    }
    float acc = sign * (acc0 + acc1);

    // ---- block reduction (fixed order over warp slots) ----
    __shared__ float sm[NWARP];
    #pragma unroll
    for (int o = 16; o > 0; o >>= 1)
        acc += __shfl_down_sync(0xffffffffu, acc, o);
    if (lid == 0) sm[wid] = acc;
    __syncthreads();

    __shared__ bool s_last;
    if (threadIdx.x == 0) {
        float v = 0.0f;
        #pragma unroll
        for (int w = 0; w < NWARP; w++) v += sm[w];
        g_partial[blk] = v;
        __threadfence();                                // publish partial
        unsigned int t = atomicAdd(&g_count, 1u);
        s_last = (t == (unsigned int)(NBLK - 1));
    }
    __syncthreads();

    // ---- last block finalizes (deterministic fixed-order sums) ----
    if (s_last) {
        float v = 0.0f;
        if (threadIdx.x < NCH) {                        // one thread / channel
            float d = 0.0f;
            #pragma unroll
            for (int k = 0; k < SPLIT; k++)
                d += g_partial[threadIdx.x * SPLIT + k];
            v = d * d;
        }
        #pragma unroll
        for (int o = 16; o > 0; o >>= 1)
            v += __shfl_down_sync(0xffffffffu, v, o);
        if (lid == 0) sm[wid] = v;
        __syncthreads();
        if (threadIdx.x == 0) {
            float t = 0.0f;
            #pragma unroll
            for (int w = 0; w < NWARP; w++) t += sm[w];
            out[0] = t * (1.0f / (128.0f * 128.0f));
            g_count = 0;                                // reset for graph replay
        }
    }
}

extern "C" void kernel_launch(void* const* d_in, const int* in_sizes, int n_in,
                              void* d_out, int out_size)
{
    const float4* in  = (const float4*)d_in[0];
    const float4* tgt = (const float4*)d_in[1];
    float* out = (float*)d_out;

    fused_loss_kernel<<<NBLK, NTHR>>>(in, tgt, out);
}

// round 10
// speedup vs baseline: 1.0183x; 1.0183x over previous
#include <cuda_runtime.h>
#include <cuda_bf16.h>
#include <cstdint>

// loss = || sum_spatial(input_c) - sum_spatial(target_c) ||^2 / C^2
// input/target: (1, 128, 512, 512) fp32 contiguous.
// Persistent grid: 592 CTAs x 512 thr grid-stride over 1024 tiles
// (tile = 128KB of each array; warps 0-7 stream `in`, 8-15 stream `tgt`,
// each warp one contiguous 16KB run). One fence+atomic per CTA.
// Last CTA finalizes with fixed-order sums (bit-deterministic).

#define NCH    128
#define HW     (512 * 512)          // 262144 elements per channel
#define SPLIT  8                    // tiles per channel
#define NTILE  (NCH * SPLIT)        // 1024 tiles
#define GRID   592                  // 148 SMs * 4 resident CTAs
#define NTHR   512
#define NWARP  (NTHR / 32)          // 16 warps

__device__ float        g_partial[NTILE];
__device__ unsigned int g_count;    // zero-init at load; last CTA resets it

__global__ __launch_bounds__(NTHR) void fused_loss_kernel(
    const float4* __restrict__ in, const float4* __restrict__ tgt,
    float* __restrict__ out)
{
    const int wid = threadIdx.x >> 5;        // 0..15
    const int lid = threadIdx.x & 31;

    const int vec_per_chan = HW / 4;                 // 65536 float4/channel
    const int vec_per_tile = vec_per_chan / SPLIT;   // 8192 float4/tile
    const int vec_per_w    = vec_per_tile / 8;       // 1024 float4/warp (16KB)

    const int sub_warp  = wid & 7;                   // 0..7 within stream
    const float4* src   = (wid < 8) ? in : tgt;
    const float  sign   = (wid < 8) ? 1.0f : -1.0f;

    __shared__ float sm[NWARP];

    // ---- persistent loop over tiles ----
    for (int t = blockIdx.x; t < NTILE; t += GRID) {
        const int c = t >> 3;                 // channel
        const int s = t & (SPLIT - 1);        // split within channel

        const float4* p = src + (size_t)c * vec_per_chan
                              + (size_t)s * vec_per_tile
                              + (size_t)sub_warp * vec_per_w;

        float acc0 = 0.0f, acc1 = 0.0f;
        #pragma unroll 8
        for (int i = lid; i < vec_per_w; i += 32) {
            float4 a = __ldg(p + i);
            acc0 += a.x + a.y;
            acc1 += a.z + a.w;
        }
        float acc = sign * (acc0 + acc1);

        // block reduction (fixed order over warp slots)
        #pragma unroll
        for (int o = 16; o > 0; o >>= 1)
            acc += __shfl_down_sync(0xffffffffu, acc, o);
        if (lid == 0) sm[wid] = acc;
        __syncthreads();
        if (threadIdx.x == 0) {
            float v = 0.0f;
            #pragma unroll
            for (int w = 0; w < NWARP; w++) v += sm[w];
            g_partial[t] = v;
        }
        __syncthreads();                      // sm reused next iteration
    }

    // ---- one publish + ticket per CTA ----
    __shared__ bool s_last;
    if (threadIdx.x == 0) {
        __threadfence();                                // publish partials
        unsigned int t = atomicAdd(&g_count, 1u);
        s_last = (t == (unsigned int)(GRID - 1));
    }
    __syncthreads();

    // ---- last CTA finalizes (deterministic fixed-order sums) ----
    if (s_last) {
        float v = 0.0f;
        if (threadIdx.x < NCH) {                        // one thread / channel
            float d = 0.0f;
            #pragma unroll
            for (int k = 0; k < SPLIT; k++)
                d += g_partial[threadIdx.x * SPLIT + k];
            v = d * d;
        }
        #pragma unroll
        for (int o = 16; o > 0; o >>= 1)
            v += __shfl_down_sync(0xffffffffu, v, o);
        if (lid == 0) sm[wid] = v;
        __syncthreads();
        if (threadIdx.x == 0) {
            float t = 0.0f;
            #pragma unroll
            for (int w = 0; w < NWARP; w++) t += sm[w];
            out[0] = t * (1.0f / (128.0f * 128.0f));
            g_count = 0;                                // reset for graph replay
        }
    }
}

extern "C" void kernel_launch(void* const* d_in, const int* in_sizes, int n_in,
                              void* d_out, int out_size)
{
    const float4* in  = (const float4*)d_in[0];
    const float4* tgt = (const float4*)d_in[1];
    float* out = (float*)d_out;

    fused_loss_kernel<<<GRID, NTHR>>>(in, tgt, out);
}